// round 11
// baseline (speedup 1.0000x reference)
#include <cuda_runtime.h>

// AttentionConv: q,k,v = 1x1 convs; per-channel softmax over 7x7 window of
// q*(k+bias); out = sum attn*v.  B=4, C=Cout=64, H=W=64, K=7, PAD=3.
//
// R11: overlap abandoned (single-wave grids retire together; PDL proven
//      neutral twice).  Consolidation: (1) qkv retiled to 128px x 64oc,
//      256 threads, 384 blocks -- halves W-staging instances and prologue
//      count, 24 warps/SM, still single wave; (2) attn zero-fill reduced
//      to actual pad regions only (12 pad cols x 22 rows + edge rows)
//      and the redundant first barrier removed.  Plain launches (no PDL).

#define LOG2E 1.4426950408889634f

__device__ float g_q[4 * 64 * 64 * 64];
__device__ float g_k[4 * 64 * 64 * 64];
__device__ float g_v[4 * 64 * 64 * 64];

__device__ __forceinline__ float ex2f(float v) {
    float r;
    asm("ex2.approx.ftz.f32 %0, %1;" : "=f"(r) : "f"(v));
    return r;
}

__device__ __forceinline__ unsigned long long fma_f32x2(
    unsigned long long a, unsigned long long b, unsigned long long c) {
    unsigned long long d;
    asm("fma.rn.f32x2 %0, %1, %2, %3;" : "=l"(d) : "l"(a), "l"(b), "l"(c));
    return d;
}

__device__ __forceinline__ unsigned long long dupf(float v) {
    unsigned long long r;
    asm("mov.b64 %0, {%1, %1};" : "=l"(r) : "f"(v));
    return r;
}

// ---------------------------------------------------------------------------
// Kernel 1: qkv projections.  256 threads, 64oc x 128px tile, 384 blocks
// (128 px-tiles x 3 mats).  ws[c][o] = W^T stride 66 (coalesced LDG +
// 2-way STS scatter, staged HALF as often as the 64px version);
// xs[c][p] 64x128.  Thread tile 8oc x 4px as 4 o-pairs -> 16 FFMA2/c.
// smem 48.9KB -> 3 blocks/SM (regs), 24 warps/SM, single wave.
// ---------------------------------------------------------------------------
#define WSTR 66

__global__ __launch_bounds__(256) void qkv_kernel(
    const float* __restrict__ x, const float* __restrict__ y,
    const float* __restrict__ Wq, const float* __restrict__ Wk,
    const float* __restrict__ Wv) {
    __shared__ __align__(16) float ws[64 * WSTR];     // 16.9 KB
    __shared__ __align__(16) float xs[64 * 128];      // 32 KB

    const int mat = blockIdx.y;
    const float* Wsrc = (mat == 0) ? Wq : ((mat == 1) ? Wk : Wv);
    const float* src  = (mat == 2) ? y : x;
    float* dst = (mat == 0) ? g_q : ((mat == 1) ? g_k : g_v);

    const int tid = threadIdx.x;
    const int pix0 = blockIdx.x << 7;      // 128 consecutive pixels, same b
    const int b = pix0 >> 12;
    const int hw0 = pix0 & 4095;

    // coalesced W read (flat o*64+c), scatter-transpose into smem
#pragma unroll
    for (int i = 0; i < 16; i++) {
        int idx = tid + i * 256;           // = o*64 + c
        ws[(idx & 63) * WSTR + (idx >> 6)] = Wsrc[idx];
    }
#pragma unroll
    for (int i = 0; i < 32; i++) {
        int idx = tid + i * 256;           // = c*128 + p
        xs[idx] = src[((b << 6) + (idx >> 7)) * 4096 + hw0 + (idx & 127)];
    }
    __syncthreads();

    const int o0 = (tid >> 5) << 3;        // 8 outputs (4 o-pairs)
    const int p0 = (tid & 31) << 2;        // 4 pixels

    unsigned long long acc[4][4];          // [o_pair][pixel]
#pragma unroll
    for (int i = 0; i < 4; i++)
#pragma unroll
        for (int j = 0; j < 4; j++) acc[i][j] = 0ULL;

#pragma unroll 4
    for (int cc = 0; cc < 64; cc++) {
        float4 xv = *(const float4*)(xs + (cc << 7) + p0);
        unsigned long long dx0 = dupf(xv.x);
        unsigned long long dx1 = dupf(xv.y);
        unsigned long long dx2 = dupf(xv.z);
        unsigned long long dx3 = dupf(xv.w);
        const float* wrow = ws + cc * WSTR + o0;
        unsigned long long wp0 = *(const unsigned long long*)(wrow);
        unsigned long long wp1 = *(const unsigned long long*)(wrow + 2);
        unsigned long long wp2 = *(const unsigned long long*)(wrow + 4);
        unsigned long long wp3 = *(const unsigned long long*)(wrow + 6);
        acc[0][0] = fma_f32x2(wp0, dx0, acc[0][0]);
        acc[0][1] = fma_f32x2(wp0, dx1, acc[0][1]);
        acc[0][2] = fma_f32x2(wp0, dx2, acc[0][2]);
        acc[0][3] = fma_f32x2(wp0, dx3, acc[0][3]);
        acc[1][0] = fma_f32x2(wp1, dx0, acc[1][0]);
        acc[1][1] = fma_f32x2(wp1, dx1, acc[1][1]);
        acc[1][2] = fma_f32x2(wp1, dx2, acc[1][2]);
        acc[1][3] = fma_f32x2(wp1, dx3, acc[1][3]);
        acc[2][0] = fma_f32x2(wp2, dx0, acc[2][0]);
        acc[2][1] = fma_f32x2(wp2, dx1, acc[2][1]);
        acc[2][2] = fma_f32x2(wp2, dx2, acc[2][2]);
        acc[2][3] = fma_f32x2(wp2, dx3, acc[2][3]);
        acc[3][0] = fma_f32x2(wp3, dx0, acc[3][0]);
        acc[3][1] = fma_f32x2(wp3, dx1, acc[3][1]);
        acc[3][2] = fma_f32x2(wp3, dx2, acc[3][2]);
        acc[3][3] = fma_f32x2(wp3, dx3, acc[3][3]);
    }

#pragma unroll
    for (int o2 = 0; o2 < 4; o2++) {
        float2 v0 = *reinterpret_cast<float2*>(&acc[o2][0]);
        float2 v1 = *reinterpret_cast<float2*>(&acc[o2][1]);
        float2 v2 = *reinterpret_cast<float2*>(&acc[o2][2]);
        float2 v3 = *reinterpret_cast<float2*>(&acc[o2][3]);
        float* base = dst + ((b << 6) + o0 + 2 * o2) * 4096 + hw0 + p0;
        *(float4*)(base)        = make_float4(v0.x, v1.x, v2.x, v3.x);
        *(float4*)(base + 4096) = make_float4(v0.y, v1.y, v2.y, v3.y);
    }
}

// ---------------------------------------------------------------------------
// Kernel 2: windowed per-channel softmax-attention.
// grid = (4 h-tiles, 64 channels, 4 batches); block = 128 threads.
// R11: zero-fill only the pad regions (cols 0-2 and 67-75 of all 22 rows,
// plus the <=3 out-of-range halo rows on edge tiles); pad and interior
// writes are disjoint -> single barrier before the mainloop.
// ---------------------------------------------------------------------------
#define KSW 76

__global__ __launch_bounds__(128, 7) void attn_kernel(
    const float* __restrict__ rel_h, const float* __restrict__ rel_w,
    float* __restrict__ out) {
    __shared__ __align__(16) float ks[22 * KSW];
    __shared__ __align__(16) float vs[22 * KSW];

    const int tid = threadIdx.x;
    const int h0 = blockIdx.x << 4;
    const int c  = blockIdx.y;
    const int b  = blockIdx.z;
    const int plane = ((b << 6) + c) << 12;

    const int ty = tid >> 4;
    const int w0 = (tid & 15) << 2;
    const int r0 = h0 + (ty << 1);

    // ---- issue ALL global loads up front ----
    const float* kp = g_k + plane;
    const float* vp = g_v + plane;
    float4 kreg[3], vreg[3];
    bool inb[3];
    int soff[3];
#pragma unroll
    for (int it = 0; it < 3; it++) {
        int i = tid + it * 128;            // 0..351 (22 rows x 16 col-groups)
        int r = i >> 4, c4 = (i & 15) << 2;
        int gr = h0 - 3 + r;
        bool valid = (i < 352) && ((unsigned)gr < 64u);
        inb[it] = valid;
        soff[it] = r * KSW + 3 + c4;
        if (valid) {
            kreg[it] = *(const float4*)(kp + (gr << 6) + c4);
            vreg[it] = *(const float4*)(vp + (gr << 6) + c4);
        }
    }
    const float4 qa = *(const float4*)(g_q + plane + (r0 << 6) + w0);
    const float4 qb = *(const float4*)(g_q + plane + ((r0 + 1) << 6) + w0);

    const float* bp = (c < 32) ? (rel_h + c * 7) : (rel_w + (c - 32) * 7);
    float bias7[7];
#pragma unroll
    for (int j = 0; j < 7; j++) bias7[j] = __ldg(bp + j);

    // ---- zero ONLY the pad regions (disjoint from interior commits) ----
    // side pads: cols 0,1,2 and 67..75 for all 22 rows (12 cols x 22 rows)
    for (int i = tid; i < 264; i += 128) {
        int r = i / 12, cc = i % 12;
        int col = (cc < 3) ? cc : (64 + cc);   // 3..11 -> 67..75
        ks[r * KSW + col] = 0.0f;
        vs[r * KSW + col] = 0.0f;
    }
    // out-of-range halo rows (edge tiles only): rows 0-2 (h0=0), 19-21 (h0=48)
    if (h0 == 0) {
        for (int i = tid; i < 3 * KSW; i += 128) { ks[i] = 0.0f; vs[i] = 0.0f; }
    } else if (h0 == 48) {
        for (int i = tid; i < 3 * KSW; i += 128) {
            ks[19 * KSW + i] = 0.0f;
            vs[19 * KSW + i] = 0.0f;
        }
    }

    // ---- commit interior values (cols 3..66, in-range rows) ----
#pragma unroll
    for (int it = 0; it < 3; it++) {
        if (inb[it]) {
            int s0 = soff[it];
            ks[s0] = kreg[it].x; ks[s0 + 1] = kreg[it].y;
            ks[s0 + 2] = kreg[it].z; ks[s0 + 3] = kreg[it].w;
            vs[s0] = vreg[it].x; vs[s0 + 1] = vreg[it].y;
            vs[s0 + 2] = vreg[it].z; vs[s0 + 3] = vreg[it].w;
        }
    }
    __syncthreads();

    float q2[8] = {qa.x * LOG2E, qa.y * LOG2E, qa.z * LOG2E, qa.w * LOG2E,
                   qb.x * LOG2E, qb.y * LOG2E, qb.z * LOG2E, qb.w * LOG2E};
    float s[8], a[8];
#pragma unroll
    for (int i = 0; i < 8; i++) { s[i] = 0.f; a[i] = 0.f; }

    if (c < 32) {
#pragma unroll
        for (int j = 0; j < 8; j++) {
            const float* krow = &ks[((ty << 1) + j) * KSW + w0];
            const float* vrow = &vs[((ty << 1) + j) * KSW + w0];
            float kr[12], vr[12];
            *(float4*)(kr)     = *(const float4*)(krow);
            *(float4*)(kr + 4) = *(const float4*)(krow + 4);
            *(float4*)(kr + 8) = *(const float4*)(krow + 8);
            *(float4*)(vr)     = *(const float4*)(vrow);
            *(float4*)(vr + 4) = *(const float4*)(vrow + 4);
            *(float4*)(vr + 8) = *(const float4*)(vrow + 8);
            if (j < 7) {
                float qb0[4];
#pragma unroll
                for (int i = 0; i < 4; i++) qb0[i] = q2[i] * bias7[j];
#pragma unroll
                for (int kw = 0; kw < 7; kw++)
#pragma unroll
                    for (int i = 0; i < 4; i++) {
                        float e = ex2f(fmaf(q2[i], kr[i + kw], qb0[i]));
                        s[i] += e;
                        a[i] = fmaf(e, vr[i + kw], a[i]);
                    }
            }
            if (j >= 1) {
                float qb1[4];
#pragma unroll
                for (int i = 0; i < 4; i++) qb1[i] = q2[4 + i] * bias7[j - 1];
#pragma unroll
                for (int kw = 0; kw < 7; kw++)
#pragma unroll
                    for (int i = 0; i < 4; i++) {
                        float e = ex2f(fmaf(q2[4 + i], kr[i + kw], qb1[i]));
                        s[4 + i] += e;
                        a[4 + i] = fmaf(e, vr[i + kw], a[4 + i]);
                    }
            }
        }
    } else {
#pragma unroll
        for (int j = 0; j < 8; j++) {
            const float* krow = &ks[((ty << 1) + j) * KSW + w0];
            const float* vrow = &vs[((ty << 1) + j) * KSW + w0];
            float kr[12], vr[12];
            *(float4*)(kr)     = *(const float4*)(krow);
            *(float4*)(kr + 4) = *(const float4*)(krow + 4);
            *(float4*)(kr + 8) = *(const float4*)(krow + 8);
            *(float4*)(vr)     = *(const float4*)(vrow);
            *(float4*)(vr + 4) = *(const float4*)(vrow + 4);
            *(float4*)(vr + 8) = *(const float4*)(vrow + 8);
            if (j < 7) {
#pragma unroll
                for (int kw = 0; kw < 7; kw++) {
                    float bb = bias7[kw];
#pragma unroll
                    for (int i = 0; i < 4; i++) {
                        float e = ex2f(q2[i] * (kr[i + kw] + bb));
                        s[i] += e;
                        a[i] = fmaf(e, vr[i + kw], a[i]);
                    }
                }
            }
            if (j >= 1) {
#pragma unroll
                for (int kw = 0; kw < 7; kw++) {
                    float bb = bias7[kw];
#pragma unroll
                    for (int i = 0; i < 4; i++) {
                        float e = ex2f(q2[4 + i] * (kr[i + kw] + bb));
                        s[4 + i] += e;
                        a[4 + i] = fmaf(e, vr[i + kw], a[4 + i]);
                    }
                }
            }
        }
    }

    float4 o0, o1;
    o0.x = __fdividef(a[0], s[0]);
    o0.y = __fdividef(a[1], s[1]);
    o0.z = __fdividef(a[2], s[2]);
    o0.w = __fdividef(a[3], s[3]);
    o1.x = __fdividef(a[4], s[4]);
    o1.y = __fdividef(a[5], s[5]);
    o1.z = __fdividef(a[6], s[6]);
    o1.w = __fdividef(a[7], s[7]);
    *(float4*)(out + plane + (r0 << 6) + w0) = o0;
    *(float4*)(out + plane + ((r0 + 1) << 6) + w0) = o1;
}

extern "C" void kernel_launch(void* const* d_in, const int* in_sizes, int n_in,
                              void* d_out, int out_size) {
    const float* x     = (const float*)d_in[0];
    const float* y     = (const float*)d_in[1];
    const float* Wq    = (const float*)d_in[2];
    const float* Wk    = (const float*)d_in[3];
    const float* Wv    = (const float*)d_in[4];
    const float* rel_h = (const float*)d_in[5];
    const float* rel_w = (const float*)d_in[6];
    float* out = (float*)d_out;

    dim3 g1(128, 3, 1);
    qkv_kernel<<<g1, 256>>>(x, y, Wq, Wk, Wv);

    dim3 g2(4, 64, 4);
    attn_kernel<<<g2, 128>>>(rel_h, rel_w, out);
}

// round 12
// speedup vs baseline: 1.0349x; 1.0349x over previous
#include <cuda_runtime.h>

// AttentionConv: q,k,v = 1x1 convs; per-channel softmax over 7x7 window of
// q*(k+bias); out = sum attn*v.  B=4, C=Cout=64, H=W=64, K=7, PAD=3.
//
// R12: consolidation.  FFMA2 proven cosmetic (R3 time == scalar FFMA floor;
//      ptxas expands fma.rn.f32x2 here), so qkv mainloop is plain scalar
//      FMA with no duplication movs, R3 tiling restored (64px x 64oc, 128
//      threads, 768 blocks -- the R11 128px retile regressed).  x staging
//      vectorized (LDG.128/STS.128).  attn kept from R11 (pad-only
//      zero-fill, hoisted loads): 14.9us measured.

#define LOG2E 1.4426950408889634f

__device__ float g_q[4 * 64 * 64 * 64];
__device__ float g_k[4 * 64 * 64 * 64];
__device__ float g_v[4 * 64 * 64 * 64];

__device__ __forceinline__ float ex2f(float v) {
    float r;
    asm("ex2.approx.ftz.f32 %0, %1;" : "=f"(r) : "f"(v));
    return r;
}

// ---------------------------------------------------------------------------
// Kernel 1: qkv projections.  128 threads, 64oc x 64px tile, 768 blocks.
// ws[c][o] = W^T, stride 66 (coalesced LDG + 2-way STS scatter);
// xs[c][p] staged with LDG.128/STS.128.  Thread tile 8oc x 4px, scalar:
// per cc: 4x LDS.64 (w, broadcast) + 1x LDS.128 (x) + 32 FFMA.
// ---------------------------------------------------------------------------
#define WSTR 66

__global__ __launch_bounds__(128) void qkv_kernel(
    const float* __restrict__ x, const float* __restrict__ y,
    const float* __restrict__ Wq, const float* __restrict__ Wk,
    const float* __restrict__ Wv) {
    __shared__ __align__(16) float ws[64 * WSTR];
    __shared__ __align__(16) float xs[64 * 64];

    const int mat = blockIdx.y;
    const float* Wsrc = (mat == 0) ? Wq : ((mat == 1) ? Wk : Wv);
    const float* src  = (mat == 2) ? y : x;
    float* dst = (mat == 0) ? g_q : ((mat == 1) ? g_k : g_v);

    const int tid = threadIdx.x;
    const int pix0 = blockIdx.x * 64;
    const int b = pix0 >> 12;
    const int hw0 = pix0 & 4095;

    // W: coalesced scalar read (flat o*64+c), scatter-transpose (2-way STS)
#pragma unroll
    for (int i = 0; i < 32; i++) {
        int idx = tid + i * 128;           // = o*64 + c
        ws[(idx & 63) * WSTR + (idx >> 6)] = Wsrc[idx];
    }
    // x: vectorized stage, 8 LDG.128 + 8 STS.128
#pragma unroll
    for (int i = 0; i < 8; i++) {
        int idx4 = tid + i * 128;          // = c*16 + col4
        int c = idx4 >> 4, col4 = (idx4 & 15) << 2;
        float4 v = *(const float4*)(src + ((b << 6) + c) * 4096 + hw0 + col4);
        *(float4*)(xs + (c << 6) + col4) = v;
    }
    __syncthreads();

    const int o0 = (tid >> 4) << 3;        // 8 outputs per thread
    const int p0 = (tid & 15) << 2;        // 4 pixels per thread

    float acc[8][4];
#pragma unroll
    for (int i = 0; i < 8; i++)
#pragma unroll
        for (int j = 0; j < 4; j++) acc[i][j] = 0.f;

#pragma unroll 4
    for (int cc = 0; cc < 64; cc++) {
        float4 xv = *(const float4*)(xs + (cc << 6) + p0);
        const float* wrow = ws + cc * WSTR + o0;
        float2 w01 = *(const float2*)(wrow);
        float2 w23 = *(const float2*)(wrow + 2);
        float2 w45 = *(const float2*)(wrow + 4);
        float2 w67 = *(const float2*)(wrow + 6);
        float w[8] = {w01.x, w01.y, w23.x, w23.y, w45.x, w45.y, w67.x, w67.y};
#pragma unroll
        for (int oi = 0; oi < 8; oi++) {
            acc[oi][0] = fmaf(w[oi], xv.x, acc[oi][0]);
            acc[oi][1] = fmaf(w[oi], xv.y, acc[oi][1]);
            acc[oi][2] = fmaf(w[oi], xv.z, acc[oi][2]);
            acc[oi][3] = fmaf(w[oi], xv.w, acc[oi][3]);
        }
    }

#pragma unroll
    for (int oi = 0; oi < 8; oi++) {
        float* base = dst + ((b << 6) + o0 + oi) * 4096 + hw0 + p0;
        *(float4*)(base) =
            make_float4(acc[oi][0], acc[oi][1], acc[oi][2], acc[oi][3]);
    }
}

// ---------------------------------------------------------------------------
// Kernel 2: windowed per-channel softmax-attention (R11 version, measured
// 14.9us).  grid = (4 h-tiles, 64 channels, 4 batches); 128 threads.
// Hoisted LDG; pad-only zero-fill; single barrier; 2 rows x 4 cols/thread.
// ---------------------------------------------------------------------------
#define KSW 76

__global__ __launch_bounds__(128, 7) void attn_kernel(
    const float* __restrict__ rel_h, const float* __restrict__ rel_w,
    float* __restrict__ out) {
    __shared__ __align__(16) float ks[22 * KSW];
    __shared__ __align__(16) float vs[22 * KSW];

    const int tid = threadIdx.x;
    const int h0 = blockIdx.x << 4;
    const int c  = blockIdx.y;
    const int b  = blockIdx.z;
    const int plane = ((b << 6) + c) << 12;

    const int ty = tid >> 4;
    const int w0 = (tid & 15) << 2;
    const int r0 = h0 + (ty << 1);

    // ---- issue ALL global loads up front ----
    const float* kp = g_k + plane;
    const float* vp = g_v + plane;
    float4 kreg[3], vreg[3];
    bool inb[3];
    int soff[3];
#pragma unroll
    for (int it = 0; it < 3; it++) {
        int i = tid + it * 128;            // 0..351 (22 rows x 16 col-groups)
        int r = i >> 4, c4 = (i & 15) << 2;
        int gr = h0 - 3 + r;
        bool valid = (i < 352) && ((unsigned)gr < 64u);
        inb[it] = valid;
        soff[it] = r * KSW + 3 + c4;
        if (valid) {
            kreg[it] = *(const float4*)(kp + (gr << 6) + c4);
            vreg[it] = *(const float4*)(vp + (gr << 6) + c4);
        }
    }
    const float4 qa = *(const float4*)(g_q + plane + (r0 << 6) + w0);
    const float4 qb = *(const float4*)(g_q + plane + ((r0 + 1) << 6) + w0);

    const float* bp = (c < 32) ? (rel_h + c * 7) : (rel_w + (c - 32) * 7);
    float bias7[7];
#pragma unroll
    for (int j = 0; j < 7; j++) bias7[j] = __ldg(bp + j);

    // ---- zero ONLY the pad regions (disjoint from interior commits) ----
    for (int i = tid; i < 264; i += 128) {
        int r = i / 12, cc = i % 12;
        int col = (cc < 3) ? cc : (64 + cc);   // 3..11 -> 67..75
        ks[r * KSW + col] = 0.0f;
        vs[r * KSW + col] = 0.0f;
    }
    if (h0 == 0) {
        for (int i = tid; i < 3 * KSW; i += 128) { ks[i] = 0.0f; vs[i] = 0.0f; }
    } else if (h0 == 48) {
        for (int i = tid; i < 3 * KSW; i += 128) {
            ks[19 * KSW + i] = 0.0f;
            vs[19 * KSW + i] = 0.0f;
        }
    }

    // ---- commit interior values ----
#pragma unroll
    for (int it = 0; it < 3; it++) {
        if (inb[it]) {
            int s0 = soff[it];
            ks[s0] = kreg[it].x; ks[s0 + 1] = kreg[it].y;
            ks[s0 + 2] = kreg[it].z; ks[s0 + 3] = kreg[it].w;
            vs[s0] = vreg[it].x; vs[s0 + 1] = vreg[it].y;
            vs[s0 + 2] = vreg[it].z; vs[s0 + 3] = vreg[it].w;
        }
    }
    __syncthreads();

    float q2[8] = {qa.x * LOG2E, qa.y * LOG2E, qa.z * LOG2E, qa.w * LOG2E,
                   qb.x * LOG2E, qb.y * LOG2E, qb.z * LOG2E, qb.w * LOG2E};
    float s[8], a[8];
#pragma unroll
    for (int i = 0; i < 8; i++) { s[i] = 0.f; a[i] = 0.f; }

    if (c < 32) {
#pragma unroll
        for (int j = 0; j < 8; j++) {
            const float* krow = &ks[((ty << 1) + j) * KSW + w0];
            const float* vrow = &vs[((ty << 1) + j) * KSW + w0];
            float kr[12], vr[12];
            *(float4*)(kr)     = *(const float4*)(krow);
            *(float4*)(kr + 4) = *(const float4*)(krow + 4);
            *(float4*)(kr + 8) = *(const float4*)(krow + 8);
            *(float4*)(vr)     = *(const float4*)(vrow);
            *(float4*)(vr + 4) = *(const float4*)(vrow + 4);
            *(float4*)(vr + 8) = *(const float4*)(vrow + 8);
            if (j < 7) {
                float qb0[4];
#pragma unroll
                for (int i = 0; i < 4; i++) qb0[i] = q2[i] * bias7[j];
#pragma unroll
                for (int kw = 0; kw < 7; kw++)
#pragma unroll
                    for (int i = 0; i < 4; i++) {
                        float e = ex2f(fmaf(q2[i], kr[i + kw], qb0[i]));
                        s[i] += e;
                        a[i] = fmaf(e, vr[i + kw], a[i]);
                    }
            }
            if (j >= 1) {
                float qb1[4];
#pragma unroll
                for (int i = 0; i < 4; i++) qb1[i] = q2[4 + i] * bias7[j - 1];
#pragma unroll
                for (int kw = 0; kw < 7; kw++)
#pragma unroll
                    for (int i = 0; i < 4; i++) {
                        float e = ex2f(fmaf(q2[4 + i], kr[i + kw], qb1[i]));
                        s[4 + i] += e;
                        a[4 + i] = fmaf(e, vr[i + kw], a[4 + i]);
                    }
            }
        }
    } else {
#pragma unroll
        for (int j = 0; j < 8; j++) {
            const float* krow = &ks[((ty << 1) + j) * KSW + w0];
            const float* vrow = &vs[((ty << 1) + j) * KSW + w0];
            float kr[12], vr[12];
            *(float4*)(kr)     = *(const float4*)(krow);
            *(float4*)(kr + 4) = *(const float4*)(krow + 4);
            *(float4*)(kr + 8) = *(const float4*)(krow + 8);
            *(float4*)(vr)     = *(const float4*)(vrow);
            *(float4*)(vr + 4) = *(const float4*)(vrow + 4);
            *(float4*)(vr + 8) = *(const float4*)(vrow + 8);
            if (j < 7) {
#pragma unroll
                for (int kw = 0; kw < 7; kw++) {
                    float bb = bias7[kw];
#pragma unroll
                    for (int i = 0; i < 4; i++) {
                        float e = ex2f(q2[i] * (kr[i + kw] + bb));
                        s[i] += e;
                        a[i] = fmaf(e, vr[i + kw], a[i]);
                    }
                }
            }
            if (j >= 1) {
#pragma unroll
                for (int kw = 0; kw < 7; kw++) {
                    float bb = bias7[kw];
#pragma unroll
                    for (int i = 0; i < 4; i++) {
                        float e = ex2f(q2[4 + i] * (kr[i + kw] + bb));
                        s[4 + i] += e;
                        a[4 + i] = fmaf(e, vr[i + kw], a[4 + i]);
                    }
                }
            }
        }
    }

    float4 o0, o1;
    o0.x = __fdividef(a[0], s[0]);
    o0.y = __fdividef(a[1], s[1]);
    o0.z = __fdividef(a[2], s[2]);
    o0.w = __fdividef(a[3], s[3]);
    o1.x = __fdividef(a[4], s[4]);
    o1.y = __fdividef(a[5], s[5]);
    o1.z = __fdividef(a[6], s[6]);
    o1.w = __fdividef(a[7], s[7]);
    *(float4*)(out + plane + (r0 << 6) + w0) = o0;
    *(float4*)(out + plane + ((r0 + 1) << 6) + w0) = o1;
}

extern "C" void kernel_launch(void* const* d_in, const int* in_sizes, int n_in,
                              void* d_out, int out_size) {
    const float* x     = (const float*)d_in[0];
    const float* y     = (const float*)d_in[1];
    const float* Wq    = (const float*)d_in[2];
    const float* Wk    = (const float*)d_in[3];
    const float* Wv    = (const float*)d_in[4];
    const float* rel_h = (const float*)d_in[5];
    const float* rel_w = (const float*)d_in[6];
    float* out = (float*)d_out;

    dim3 g1(256, 3, 1);
    qkv_kernel<<<g1, 128>>>(x, y, Wq, Wk, Wv);

    dim3 g2(4, 64, 4);
    attn_kernel<<<g2, 128>>>(rel_h, rel_w, out);
}

// round 13
// speedup vs baseline: 1.0760x; 1.0398x over previous
#include <cuda_runtime.h>

// AttentionConv: q,k,v = 1x1 convs; per-channel softmax over 7x7 window of
// q*(k+bias); out = sum attn*v.  B=4, C=Cout=64, H=W=64, K=7, PAD=3.
//
// R13: qkv reverted to the R8 FFMA2 kernel verbatim (best measured 12.0us;
//      scalar variant measured 12.8).  attn: register diet for 8 blocks/SM
//      (32 warps, +14% MUFU density): k/v strips as sliding 8-float window
//      (two tap phases, shift via ALU movs) instead of 12-float arrays;
//      __launch_bounds__(128, 8) targets 64 regs.

#define LOG2E 1.4426950408889634f

__device__ float g_q[4 * 64 * 64 * 64];
__device__ float g_k[4 * 64 * 64 * 64];
__device__ float g_v[4 * 64 * 64 * 64];

__device__ __forceinline__ float ex2f(float v) {
    float r;
    asm("ex2.approx.ftz.f32 %0, %1;" : "=f"(r) : "f"(v));
    return r;
}

__device__ __forceinline__ unsigned long long fma_f32x2(
    unsigned long long a, unsigned long long b, unsigned long long c) {
    unsigned long long d;
    asm("fma.rn.f32x2 %0, %1, %2, %3;" : "=l"(d) : "l"(a), "l"(b), "l"(c));
    return d;
}

__device__ __forceinline__ unsigned long long dupf(float v) {
    unsigned long long r;
    asm("mov.b64 %0, {%1, %1};" : "=l"(r) : "f"(v));
    return r;
}

// ---------------------------------------------------------------------------
// Kernel 1: qkv projections (R8 version verbatim).  128 threads,
// 64oc x 64px tile, 768 blocks.  ws[c][o] = W^T stride 66 (coalesced LDG +
// 2-way STS scatter); xs[c][p].  Thread tile 8oc x 4px as 4 o-pairs, FFMA2.
// ---------------------------------------------------------------------------
#define WSTR 66

__global__ __launch_bounds__(128) void qkv_kernel(
    const float* __restrict__ x, const float* __restrict__ y,
    const float* __restrict__ Wq, const float* __restrict__ Wk,
    const float* __restrict__ Wv) {
    __shared__ __align__(16) float ws[64 * WSTR];
    __shared__ __align__(16) float xs[64 * 64];

    const int mat = blockIdx.y;
    const float* Wsrc = (mat == 0) ? Wq : ((mat == 1) ? Wk : Wv);
    const float* src  = (mat == 2) ? y : x;
    float* dst = (mat == 0) ? g_q : ((mat == 1) ? g_k : g_v);

    const int tid = threadIdx.x;
    const int pix0 = blockIdx.x * 64;
    const int b = pix0 >> 12;
    const int hw0 = pix0 & 4095;

#pragma unroll
    for (int i = 0; i < 32; i++) {
        int idx = tid + i * 128;           // = o*64 + c
        ws[(idx & 63) * WSTR + (idx >> 6)] = Wsrc[idx];
    }
#pragma unroll
    for (int i = 0; i < 32; i++) {
        int idx = tid + i * 128;           // = c*64 + p
        xs[idx] = src[((b << 6) + (idx >> 6)) * 4096 + hw0 + (idx & 63)];
    }
    __syncthreads();

    const int o0 = (tid >> 4) << 3;
    const int p0 = (tid & 15) << 2;

    unsigned long long acc[4][4];
#pragma unroll
    for (int i = 0; i < 4; i++)
#pragma unroll
        for (int j = 0; j < 4; j++) acc[i][j] = 0ULL;

#pragma unroll 4
    for (int cc = 0; cc < 64; cc++) {
        float4 xv = *(const float4*)(xs + (cc << 6) + p0);
        unsigned long long dx0 = dupf(xv.x);
        unsigned long long dx1 = dupf(xv.y);
        unsigned long long dx2 = dupf(xv.z);
        unsigned long long dx3 = dupf(xv.w);
        const float* wrow = ws + cc * WSTR + o0;
        unsigned long long wp0 = *(const unsigned long long*)(wrow);
        unsigned long long wp1 = *(const unsigned long long*)(wrow + 2);
        unsigned long long wp2 = *(const unsigned long long*)(wrow + 4);
        unsigned long long wp3 = *(const unsigned long long*)(wrow + 6);
        acc[0][0] = fma_f32x2(wp0, dx0, acc[0][0]);
        acc[0][1] = fma_f32x2(wp0, dx1, acc[0][1]);
        acc[0][2] = fma_f32x2(wp0, dx2, acc[0][2]);
        acc[0][3] = fma_f32x2(wp0, dx3, acc[0][3]);
        acc[1][0] = fma_f32x2(wp1, dx0, acc[1][0]);
        acc[1][1] = fma_f32x2(wp1, dx1, acc[1][1]);
        acc[1][2] = fma_f32x2(wp1, dx2, acc[1][2]);
        acc[1][3] = fma_f32x2(wp1, dx3, acc[1][3]);
        acc[2][0] = fma_f32x2(wp2, dx0, acc[2][0]);
        acc[2][1] = fma_f32x2(wp2, dx1, acc[2][1]);
        acc[2][2] = fma_f32x2(wp2, dx2, acc[2][2]);
        acc[2][3] = fma_f32x2(wp2, dx3, acc[2][3]);
        acc[3][0] = fma_f32x2(wp3, dx0, acc[3][0]);
        acc[3][1] = fma_f32x2(wp3, dx1, acc[3][1]);
        acc[3][2] = fma_f32x2(wp3, dx2, acc[3][2]);
        acc[3][3] = fma_f32x2(wp3, dx3, acc[3][3]);
    }

#pragma unroll
    for (int o2 = 0; o2 < 4; o2++) {
        float2 v0 = *reinterpret_cast<float2*>(&acc[o2][0]);
        float2 v1 = *reinterpret_cast<float2*>(&acc[o2][1]);
        float2 v2 = *reinterpret_cast<float2*>(&acc[o2][2]);
        float2 v3 = *reinterpret_cast<float2*>(&acc[o2][3]);
        float* base = dst + ((b << 6) + o0 + 2 * o2) * 4096 + hw0 + p0;
        *(float4*)(base)        = make_float4(v0.x, v1.x, v2.x, v3.x);
        *(float4*)(base + 4096) = make_float4(v0.y, v1.y, v2.y, v3.y);
    }
}

// ---------------------------------------------------------------------------
// Kernel 2: windowed per-channel softmax-attention.
// grid = (4 h-tiles, 64 channels, 4 batches); 128 threads, 8 blocks/SM.
// Hoisted LDG, pad-only zero-fill.  k/v strips as sliding 8-float window:
// phase A (kw 0-3, idx<=6), shift+reload, phase B (kw 4-6, idx i+kw-4<=5).
// ---------------------------------------------------------------------------
#define KSW 76

__global__ __launch_bounds__(128, 8) void attn_kernel(
    const float* __restrict__ rel_h, const float* __restrict__ rel_w,
    float* __restrict__ out) {
    __shared__ __align__(16) float ks[22 * KSW];
    __shared__ __align__(16) float vs[22 * KSW];

    const int tid = threadIdx.x;
    const int h0 = blockIdx.x << 4;
    const int c  = blockIdx.y;
    const int b  = blockIdx.z;
    const int plane = ((b << 6) + c) << 12;

    const int ty = tid >> 4;
    const int w0 = (tid & 15) << 2;
    const int r0 = h0 + (ty << 1);

    // ---- issue ALL global loads up front ----
    const float* kp = g_k + plane;
    const float* vp = g_v + plane;
    float4 kreg[3], vreg[3];
    bool inb[3];
    int soff[3];
#pragma unroll
    for (int it = 0; it < 3; it++) {
        int i = tid + it * 128;            // 0..351 (22 rows x 16 col-groups)
        int r = i >> 4, c4 = (i & 15) << 2;
        int gr = h0 - 3 + r;
        bool valid = (i < 352) && ((unsigned)gr < 64u);
        inb[it] = valid;
        soff[it] = r * KSW + 3 + c4;
        if (valid) {
            kreg[it] = *(const float4*)(kp + (gr << 6) + c4);
            vreg[it] = *(const float4*)(vp + (gr << 6) + c4);
        }
    }
    const float4 qa = *(const float4*)(g_q + plane + (r0 << 6) + w0);
    const float4 qb = *(const float4*)(g_q + plane + ((r0 + 1) << 6) + w0);

    const float* bp = (c < 32) ? (rel_h + c * 7) : (rel_w + (c - 32) * 7);
    float bias7[7];
#pragma unroll
    for (int j = 0; j < 7; j++) bias7[j] = __ldg(bp + j);

    // ---- zero ONLY the pad regions ----
    for (int i = tid; i < 264; i += 128) {
        int r = i / 12, cc = i % 12;
        int col = (cc < 3) ? cc : (64 + cc);   // 3..11 -> 67..75
        ks[r * KSW + col] = 0.0f;
        vs[r * KSW + col] = 0.0f;
    }
    if (h0 == 0) {
        for (int i = tid; i < 3 * KSW; i += 128) { ks[i] = 0.0f; vs[i] = 0.0f; }
    } else if (h0 == 48) {
        for (int i = tid; i < 3 * KSW; i += 128) {
            ks[19 * KSW + i] = 0.0f;
            vs[19 * KSW + i] = 0.0f;
        }
    }

    // ---- commit interior values ----
#pragma unroll
    for (int it = 0; it < 3; it++) {
        if (inb[it]) {
            int s0 = soff[it];
            ks[s0] = kreg[it].x; ks[s0 + 1] = kreg[it].y;
            ks[s0 + 2] = kreg[it].z; ks[s0 + 3] = kreg[it].w;
            vs[s0] = vreg[it].x; vs[s0 + 1] = vreg[it].y;
            vs[s0 + 2] = vreg[it].z; vs[s0 + 3] = vreg[it].w;
        }
    }
    __syncthreads();

    float q2[8] = {qa.x * LOG2E, qa.y * LOG2E, qa.z * LOG2E, qa.w * LOG2E,
                   qb.x * LOG2E, qb.y * LOG2E, qb.z * LOG2E, qb.w * LOG2E};
    float s[8], a[8];
#pragma unroll
    for (int i = 0; i < 8; i++) { s[i] = 0.f; a[i] = 0.f; }

    if (c < 32) {
#pragma unroll
        for (int j = 0; j < 8; j++) {
            const float* krow = &ks[((ty << 1) + j) * KSW + w0];
            const float* vrow = &vs[((ty << 1) + j) * KSW + w0];
            float kr[8], vr[8];
            *(float4*)(kr)     = *(const float4*)(krow);
            *(float4*)(kr + 4) = *(const float4*)(krow + 4);
            *(float4*)(vr)     = *(const float4*)(vrow);
            *(float4*)(vr + 4) = *(const float4*)(vrow + 4);
            float qb0[4], qb1[4];
#pragma unroll
            for (int i = 0; i < 4; i++) {
                qb0[i] = (j < 7) ? q2[i] * bias7[j] : 0.f;
                qb1[i] = (j >= 1) ? q2[4 + i] * bias7[j - 1] : 0.f;
            }
            // phase A: kw 0..3 (indices i+kw <= 6)
#pragma unroll
            for (int kw = 0; kw < 4; kw++) {
                if (j < 7)
#pragma unroll
                    for (int i = 0; i < 4; i++) {
                        float e = ex2f(fmaf(q2[i], kr[i + kw], qb0[i]));
                        s[i] += e;
                        a[i] = fmaf(e, vr[i + kw], a[i]);
                    }
                if (j >= 1)
#pragma unroll
                    for (int i = 0; i < 4; i++) {
                        float e = ex2f(fmaf(q2[4 + i], kr[i + kw], qb1[i]));
                        s[4 + i] += e;
                        a[4 + i] = fmaf(e, vr[i + kw], a[4 + i]);
                    }
            }
            // shift window and reload tail
#pragma unroll
            for (int t = 0; t < 4; t++) { kr[t] = kr[t + 4]; vr[t] = vr[t + 4]; }
            *(float4*)(kr + 4) = *(const float4*)(krow + 8);
            *(float4*)(vr + 4) = *(const float4*)(vrow + 8);
            // phase B: kw 4..6 (indices i+kw-4 <= 5)
#pragma unroll
            for (int kw = 4; kw < 7; kw++) {
                if (j < 7)
#pragma unroll
                    for (int i = 0; i < 4; i++) {
                        float e = ex2f(fmaf(q2[i], kr[i + kw - 4], qb0[i]));
                        s[i] += e;
                        a[i] = fmaf(e, vr[i + kw - 4], a[i]);
                    }
                if (j >= 1)
#pragma unroll
                    for (int i = 0; i < 4; i++) {
                        float e = ex2f(fmaf(q2[4 + i], kr[i + kw - 4], qb1[i]));
                        s[4 + i] += e;
                        a[4 + i] = fmaf(e, vr[i + kw - 4], a[4 + i]);
                    }
            }
        }
    } else {
#pragma unroll
        for (int j = 0; j < 8; j++) {
            const float* krow = &ks[((ty << 1) + j) * KSW + w0];
            const float* vrow = &vs[((ty << 1) + j) * KSW + w0];
            float kr[8], vr[8];
            *(float4*)(kr)     = *(const float4*)(krow);
            *(float4*)(kr + 4) = *(const float4*)(krow + 4);
            *(float4*)(vr)     = *(const float4*)(vrow);
            *(float4*)(vr + 4) = *(const float4*)(vrow + 4);
            // phase A: kw 0..3
#pragma unroll
            for (int kw = 0; kw < 4; kw++) {
                float bb = bias7[kw];
                if (j < 7)
#pragma unroll
                    for (int i = 0; i < 4; i++) {
                        float e = ex2f(q2[i] * (kr[i + kw] + bb));
                        s[i] += e;
                        a[i] = fmaf(e, vr[i + kw], a[i]);
                    }
                if (j >= 1)
#pragma unroll
                    for (int i = 0; i < 4; i++) {
                        float e = ex2f(q2[4 + i] * (kr[i + kw] + bb));
                        s[4 + i] += e;
                        a[4 + i] = fmaf(e, vr[i + kw], a[4 + i]);
                    }
            }
#pragma unroll
            for (int t = 0; t < 4; t++) { kr[t] = kr[t + 4]; vr[t] = vr[t + 4]; }
            *(float4*)(kr + 4) = *(const float4*)(krow + 8);
            *(float4*)(vr + 4) = *(const float4*)(vrow + 8);
            // phase B: kw 4..6
#pragma unroll
            for (int kw = 4; kw < 7; kw++) {
                float bb = bias7[kw];
                if (j < 7)
#pragma unroll
                    for (int i = 0; i < 4; i++) {
                        float e = ex2f(q2[i] * (kr[i + kw - 4] + bb));
                        s[i] += e;
                        a[i] = fmaf(e, vr[i + kw - 4], a[i]);
                    }
                if (j >= 1)
#pragma unroll
                    for (int i = 0; i < 4; i++) {
                        float e = ex2f(q2[4 + i] * (kr[i + kw - 4] + bb));
                        s[4 + i] += e;
                        a[4 + i] = fmaf(e, vr[i + kw - 4], a[4 + i]);
                    }
            }
        }
    }

    float4 o0, o1;
    o0.x = __fdividef(a[0], s[0]);
    o0.y = __fdividef(a[1], s[1]);
    o0.z = __fdividef(a[2], s[2]);
    o0.w = __fdividef(a[3], s[3]);
    o1.x = __fdividef(a[4], s[4]);
    o1.y = __fdividef(a[5], s[5]);
    o1.z = __fdividef(a[6], s[6]);
    o1.w = __fdividef(a[7], s[7]);
    *(float4*)(out + plane + (r0 << 6) + w0) = o0;
    *(float4*)(out + plane + ((r0 + 1) << 6) + w0) = o1;
}

extern "C" void kernel_launch(void* const* d_in, const int* in_sizes, int n_in,
                              void* d_out, int out_size) {
    const float* x     = (const float*)d_in[0];
    const float* y     = (const float*)d_in[1];
    const float* Wq    = (const float*)d_in[2];
    const float* Wk    = (const float*)d_in[3];
    const float* Wv    = (const float*)d_in[4];
    const float* rel_h = (const float*)d_in[5];
    const float* rel_w = (const float*)d_in[6];
    float* out = (float*)d_out;

    dim3 g1(256, 3, 1);
    qkv_kernel<<<g1, 128>>>(x, y, Wq, Wk, Wv);

    dim3 g2(4, 64, 4);
    attn_kernel<<<g2, 128>>>(rel_h, rel_w, out);
}

// round 14
// speedup vs baseline: 1.1111x; 1.0326x over previous
#include <cuda_runtime.h>

// AttentionConv: q,k,v = 1x1 convs; per-channel softmax over 7x7 window of
// q*(k+bias); out = sum attn*v.  B=4, C=Cout=64, H=W=64, K=7, PAD=3.
//
// R14: attn occupancy was grid-limited (1024 blocks = 6.9/SM; regs=64 gave
//      nothing).  attn retiled to 8-row blocks: grid (8,64,4) = 2048
//      blocks, thread = 1 row x 4 cols, 14-row halo.  Wave 1 fills 8
//      blocks/SM (32 warps).  Sliding window reverted (neutral); straight
//      12-float strips.  qkv = R8 FFMA2 kernel verbatim (best measured).

#define LOG2E 1.4426950408889634f

__device__ float g_q[4 * 64 * 64 * 64];
__device__ float g_k[4 * 64 * 64 * 64];
__device__ float g_v[4 * 64 * 64 * 64];

__device__ __forceinline__ float ex2f(float v) {
    float r;
    asm("ex2.approx.ftz.f32 %0, %1;" : "=f"(r) : "f"(v));
    return r;
}

__device__ __forceinline__ unsigned long long fma_f32x2(
    unsigned long long a, unsigned long long b, unsigned long long c) {
    unsigned long long d;
    asm("fma.rn.f32x2 %0, %1, %2, %3;" : "=l"(d) : "l"(a), "l"(b), "l"(c));
    return d;
}

__device__ __forceinline__ unsigned long long dupf(float v) {
    unsigned long long r;
    asm("mov.b64 %0, {%1, %1};" : "=l"(r) : "f"(v));
    return r;
}

// ---------------------------------------------------------------------------
// Kernel 1: qkv projections (R8 version verbatim).  128 threads,
// 64oc x 64px tile, 768 blocks.  ws[c][o] = W^T stride 66; xs[c][p].
// Thread tile 8oc x 4px as 4 o-pairs, FFMA2.
// ---------------------------------------------------------------------------
#define WSTR 66

__global__ __launch_bounds__(128) void qkv_kernel(
    const float* __restrict__ x, const float* __restrict__ y,
    const float* __restrict__ Wq, const float* __restrict__ Wk,
    const float* __restrict__ Wv) {
    __shared__ __align__(16) float ws[64 * WSTR];
    __shared__ __align__(16) float xs[64 * 64];

    const int mat = blockIdx.y;
    const float* Wsrc = (mat == 0) ? Wq : ((mat == 1) ? Wk : Wv);
    const float* src  = (mat == 2) ? y : x;
    float* dst = (mat == 0) ? g_q : ((mat == 1) ? g_k : g_v);

    const int tid = threadIdx.x;
    const int pix0 = blockIdx.x * 64;
    const int b = pix0 >> 12;
    const int hw0 = pix0 & 4095;

#pragma unroll
    for (int i = 0; i < 32; i++) {
        int idx = tid + i * 128;           // = o*64 + c
        ws[(idx & 63) * WSTR + (idx >> 6)] = Wsrc[idx];
    }
#pragma unroll
    for (int i = 0; i < 32; i++) {
        int idx = tid + i * 128;           // = c*64 + p
        xs[idx] = src[((b << 6) + (idx >> 6)) * 4096 + hw0 + (idx & 63)];
    }
    __syncthreads();

    const int o0 = (tid >> 4) << 3;
    const int p0 = (tid & 15) << 2;

    unsigned long long acc[4][4];
#pragma unroll
    for (int i = 0; i < 4; i++)
#pragma unroll
        for (int j = 0; j < 4; j++) acc[i][j] = 0ULL;

#pragma unroll 4
    for (int cc = 0; cc < 64; cc++) {
        float4 xv = *(const float4*)(xs + (cc << 6) + p0);
        unsigned long long dx0 = dupf(xv.x);
        unsigned long long dx1 = dupf(xv.y);
        unsigned long long dx2 = dupf(xv.z);
        unsigned long long dx3 = dupf(xv.w);
        const float* wrow = ws + cc * WSTR + o0;
        unsigned long long wp0 = *(const unsigned long long*)(wrow);
        unsigned long long wp1 = *(const unsigned long long*)(wrow + 2);
        unsigned long long wp2 = *(const unsigned long long*)(wrow + 4);
        unsigned long long wp3 = *(const unsigned long long*)(wrow + 6);
        acc[0][0] = fma_f32x2(wp0, dx0, acc[0][0]);
        acc[0][1] = fma_f32x2(wp0, dx1, acc[0][1]);
        acc[0][2] = fma_f32x2(wp0, dx2, acc[0][2]);
        acc[0][3] = fma_f32x2(wp0, dx3, acc[0][3]);
        acc[1][0] = fma_f32x2(wp1, dx0, acc[1][0]);
        acc[1][1] = fma_f32x2(wp1, dx1, acc[1][1]);
        acc[1][2] = fma_f32x2(wp1, dx2, acc[1][2]);
        acc[1][3] = fma_f32x2(wp1, dx3, acc[1][3]);
        acc[2][0] = fma_f32x2(wp2, dx0, acc[2][0]);
        acc[2][1] = fma_f32x2(wp2, dx1, acc[2][1]);
        acc[2][2] = fma_f32x2(wp2, dx2, acc[2][2]);
        acc[2][3] = fma_f32x2(wp2, dx3, acc[2][3]);
        acc[3][0] = fma_f32x2(wp3, dx0, acc[3][0]);
        acc[3][1] = fma_f32x2(wp3, dx1, acc[3][1]);
        acc[3][2] = fma_f32x2(wp3, dx2, acc[3][2]);
        acc[3][3] = fma_f32x2(wp3, dx3, acc[3][3]);
    }

#pragma unroll
    for (int o2 = 0; o2 < 4; o2++) {
        float2 v0 = *reinterpret_cast<float2*>(&acc[o2][0]);
        float2 v1 = *reinterpret_cast<float2*>(&acc[o2][1]);
        float2 v2 = *reinterpret_cast<float2*>(&acc[o2][2]);
        float2 v3 = *reinterpret_cast<float2*>(&acc[o2][3]);
        float* base = dst + ((b << 6) + o0 + 2 * o2) * 4096 + hw0 + p0;
        *(float4*)(base)        = make_float4(v0.x, v1.x, v2.x, v3.x);
        *(float4*)(base + 4096) = make_float4(v0.y, v1.y, v2.y, v3.y);
    }
}

// ---------------------------------------------------------------------------
// Kernel 2: windowed per-channel softmax-attention.
// grid = (8 h-tiles, 64 channels, 4 batches) = 2048 blocks; 128 threads.
// Block: 8 rows x 64 cols; thread: 1 row x 4 cols; 14-row halo (stride 76).
// Hoisted LDG (2 predicated float4-pairs/thread), pad-only zero-fill.
// ---------------------------------------------------------------------------
#define KSW 76

__global__ __launch_bounds__(128, 8) void attn_kernel(
    const float* __restrict__ rel_h, const float* __restrict__ rel_w,
    float* __restrict__ out) {
    __shared__ __align__(16) float ks[14 * KSW];
    __shared__ __align__(16) float vs[14 * KSW];

    const int tid = threadIdx.x;
    const int h0 = blockIdx.x << 3;        // 8-row tile
    const int c  = blockIdx.y;
    const int b  = blockIdx.z;
    const int plane = ((b << 6) + c) << 12;

    const int ty = tid >> 4;               // 0..7 output row in tile
    const int w0 = (tid & 15) << 2;        // 4 outputs along w
    const int r0 = h0 + ty;

    // ---- issue ALL global loads up front ----
    const float* kp = g_k + plane;
    const float* vp = g_v + plane;
    float4 kreg[2], vreg[2];
    bool inb[2];
    int soff[2];
#pragma unroll
    for (int it = 0; it < 2; it++) {
        int i = tid + it * 128;            // 0..223 (14 rows x 16 col-groups)
        int r = i >> 4, c4 = (i & 15) << 2;
        int gr = h0 - 3 + r;
        bool valid = (i < 224) && ((unsigned)gr < 64u);
        inb[it] = valid;
        soff[it] = r * KSW + 3 + c4;
        if (valid) {
            kreg[it] = *(const float4*)(kp + (gr << 6) + c4);
            vreg[it] = *(const float4*)(vp + (gr << 6) + c4);
        }
    }
    const float4 q4 = *(const float4*)(g_q + plane + (r0 << 6) + w0);

    const float* bp = (c < 32) ? (rel_h + c * 7) : (rel_w + (c - 32) * 7);
    float bias7[7];
#pragma unroll
    for (int j = 0; j < 7; j++) bias7[j] = __ldg(bp + j);

    // ---- zero ONLY the pad regions ----
    // side pads: cols 0-2 and 67-75 for all 14 rows (12 x 14 = 168)
    for (int i = tid; i < 168; i += 128) {
        int r = i / 12, cc = i % 12;
        int col = (cc < 3) ? cc : (64 + cc);   // 3..11 -> 67..75
        ks[r * KSW + col] = 0.0f;
        vs[r * KSW + col] = 0.0f;
    }
    // out-of-range halo rows: h0=0 -> rows 0-2; h0=56 -> rows 11-13
    if (h0 == 0) {
        for (int i = tid; i < 3 * KSW; i += 128) { ks[i] = 0.0f; vs[i] = 0.0f; }
    } else if (h0 == 56) {
        for (int i = tid; i < 3 * KSW; i += 128) {
            ks[11 * KSW + i] = 0.0f;
            vs[11 * KSW + i] = 0.0f;
        }
    }

    // ---- commit interior values ----
#pragma unroll
    for (int it = 0; it < 2; it++) {
        if (inb[it]) {
            int s0 = soff[it];
            ks[s0] = kreg[it].x; ks[s0 + 1] = kreg[it].y;
            ks[s0 + 2] = kreg[it].z; ks[s0 + 3] = kreg[it].w;
            vs[s0] = vreg[it].x; vs[s0 + 1] = vreg[it].y;
            vs[s0 + 2] = vreg[it].z; vs[s0 + 3] = vreg[it].w;
        }
    }
    __syncthreads();

    float q2[4] = {q4.x * LOG2E, q4.y * LOG2E, q4.z * LOG2E, q4.w * LOG2E};
    float s[4] = {0.f, 0.f, 0.f, 0.f};
    float a[4] = {0.f, 0.f, 0.f, 0.f};

    if (c < 32) {
        // bias depends on kh only: hoist q2*bias out of the kw loop
#pragma unroll
        for (int j = 0; j < 7; j++) {
            const float* krow = &ks[(ty + j) * KSW + w0];
            const float* vrow = &vs[(ty + j) * KSW + w0];
            float kr[12], vr[12];
            *(float4*)(kr)     = *(const float4*)(krow);
            *(float4*)(kr + 4) = *(const float4*)(krow + 4);
            *(float4*)(kr + 8) = *(const float4*)(krow + 8);
            *(float4*)(vr)     = *(const float4*)(vrow);
            *(float4*)(vr + 4) = *(const float4*)(vrow + 4);
            *(float4*)(vr + 8) = *(const float4*)(vrow + 8);
            float qb0[4];
#pragma unroll
            for (int i = 0; i < 4; i++) qb0[i] = q2[i] * bias7[j];
#pragma unroll
            for (int kw = 0; kw < 7; kw++)
#pragma unroll
                for (int i = 0; i < 4; i++) {
                    float e = ex2f(fmaf(q2[i], kr[i + kw], qb0[i]));
                    s[i] += e;
                    a[i] = fmaf(e, vr[i + kw], a[i]);
                }
        }
    } else {
        // bias depends on kw only
#pragma unroll
        for (int j = 0; j < 7; j++) {
            const float* krow = &ks[(ty + j) * KSW + w0];
            const float* vrow = &vs[(ty + j) * KSW + w0];
            float kr[12], vr[12];
            *(float4*)(kr)     = *(const float4*)(krow);
            *(float4*)(kr + 4) = *(const float4*)(krow + 4);
            *(float4*)(kr + 8) = *(const float4*)(krow + 8);
            *(float4*)(vr)     = *(const float4*)(vrow);
            *(float4*)(vr + 4) = *(const float4*)(vrow + 4);
            *(float4*)(vr + 8) = *(const float4*)(vrow + 8);
#pragma unroll
            for (int kw = 0; kw < 7; kw++) {
                float bb = bias7[kw];
#pragma unroll
                for (int i = 0; i < 4; i++) {
                    float e = ex2f(q2[i] * (kr[i + kw] + bb));
                    s[i] += e;
                    a[i] = fmaf(e, vr[i + kw], a[i]);
                }
            }
        }
    }

    float4 o4;
    o4.x = __fdividef(a[0], s[0]);
    o4.y = __fdividef(a[1], s[1]);
    o4.z = __fdividef(a[2], s[2]);
    o4.w = __fdividef(a[3], s[3]);
    *(float4*)(out + plane + (r0 << 6) + w0) = o4;
}

extern "C" void kernel_launch(void* const* d_in, const int* in_sizes, int n_in,
                              void* d_out, int out_size) {
    const float* x     = (const float*)d_in[0];
    const float* y     = (const float*)d_in[1];
    const float* Wq    = (const float*)d_in[2];
    const float* Wk    = (const float*)d_in[3];
    const float* Wv    = (const float*)d_in[4];
    const float* rel_h = (const float*)d_in[5];
    const float* rel_w = (const float*)d_in[6];
    float* out = (float*)d_out;

    dim3 g1(256, 3, 1);
    qkv_kernel<<<g1, 128>>>(x, y, Wq, Wk, Wv);

    dim3 g2(8, 64, 4);
    attn_kernel<<<g2, 128>>>(rel_h, rel_w, out);
}